// round 12
// baseline (speedup 1.0000x reference)
#include <cuda_runtime.h>
#include <cstdint>

#define DIMC   512
#define BC     512
#define KC     128
#define EPSF   1e-6f
#define MARGINF 2.0f

// ---------------- scratch (static device globals: allocation-free) ----------------
__device__ __align__(16) float  g_head[BC * DIMC];   // transformed head vectors
__device__ __align__(16) float4 g_meta[BC];          // (h0, h1, nh, bias_head[u])

__device__ __forceinline__ float softplusf(float x) {
    return (x > 20.f) ? x : log1pf(expf(x));
}

__device__ __forceinline__ uint32_t smem_u32(const void* p) {
    return (uint32_t)__cvta_generic_to_shared(p);
}

__device__ __forceinline__ void mbar_init(uint32_t mbar, uint32_t count) {
    asm volatile("mbarrier.init.shared.b64 [%0], %1;" :: "r"(mbar), "r"(count) : "memory");
}
__device__ __forceinline__ void mbar_expect_tx(uint32_t mbar, uint32_t bytes) {
    asm volatile("mbarrier.arrive.expect_tx.shared.b64 _, [%0], %1;"
                 :: "r"(mbar), "r"(bytes) : "memory");
}
__device__ __forceinline__ void tma_bulk_g2s(uint32_t dst, const void* src,
                                             uint32_t bytes, uint32_t mbar) {
    asm volatile("cp.async.bulk.shared::cta.global.mbarrier::complete_tx::bytes "
                 "[%0], [%1], %2, [%3];"
                 :: "r"(dst), "l"(src), "r"(bytes), "r"(mbar) : "memory");
}
__device__ __forceinline__ void mbar_wait(uint32_t mbar, uint32_t parity) {
    asm volatile(
        "{\n\t"
        ".reg .pred P;\n\t"
        "WAIT_%=: \n\t"
        "mbarrier.try_wait.parity.acquire.cta.shared::cta.b64 P, [%0], %1, 0x989680;\n\t"
        "@!P bra WAIT_%=;\n\t"
        "}"
        :: "r"(mbar), "r"(parity) : "memory");
}

// ================= kernel 1: head preprocessing (one block per b) =================
#define P_TPB 256
__global__ __launch_bounds__(P_TPB)
void head_prep_kernel(const float* __restrict__ emb,
                      const float* __restrict__ rel_boost,
                      const float* __restrict__ rot_left,
                      const float* __restrict__ rot_right,
                      const float* __restrict__ bias_head,
                      const int*   __restrict__ u_idx,
                      const int*   __restrict__ r_idx)
{
    __shared__ float red[8];
    __shared__ float exch[4];

    const int b    = blockIdx.x;
    const int tid  = threadIdx.x;
    const int lane = tid & 31;
    const int warp = tid >> 5;
    const int u    = u_idx[b];
    const int r    = r_idx[b];

    const float* hrow = emb + (size_t)u * DIMC;
    float x0 = hrow[2 * tid];
    float x1 = hrow[2 * tid + 1];
    float g0 = rot_right[(size_t)r * DIMC + 2 * tid];
    float g1 = rot_right[(size_t)r * DIMC + 2 * tid + 1];
    float l0 = rot_left[(size_t)r * DIMC + 2 * tid];
    float l1 = rot_left[(size_t)r * DIMC + 2 * tid + 1];
    float rb0 = 0.f, rb1 = 0.f;
    if (tid == 0 || tid == P_TPB - 1) {
        rb0 = rel_boost[2 * r];
        rb1 = rel_boost[2 * r + 1];
    }

    if (tid == 0) x0 = 0.f;                               // proj_tan0
    float acc = (tid == 0) ? (-x1 * x1) : (x0 * x0 + x1 * x1);
    #pragma unroll
    for (int o = 16; o; o >>= 1) acc += __shfl_xor_sync(0xffffffffu, acc, o);
    if (lane == 0) red[warp] = acc;
    __syncthreads();
    float a = 0.f;
    #pragma unroll
    for (int w = 0; w < 8; ++w) a += red[w];

    float c, s;
    if (a > 0.f) {
        float sp = sqrtf(fmaxf(a, EPSF));
        c = coshf(sp);  s = sinhf(sp) / sp;
    } else {
        float st = sqrtf(fmaxf(-a, EPSF));
        c = cosf(st);   s = sinf(st) / st;
    }
    float y0 = (tid == 0) ? c : s * x0;
    float y1 = s * x1;

    // givens_rotations with rot_right
    float z0, z1;
    {
        float n  = fmaxf(sqrtf(g0 * g0 + g1 * g1), 1e-15f);
        float cr = g0 / n, sr = g1 / n;
        z0 = cr * y0 - sr * y1;
        z1 = cr * y1 + sr * y0;
    }

    // Lorentz boost: mixes dims {0,1} (thread 0) with {510,511} (thread 255)
    if (tid == 0)          { exch[0] = z0; exch[1] = z1; }
    if (tid == P_TPB - 1)  { exch[2] = z0; exch[3] = z1; }
    __syncthreads();
    if (tid == 0 || tid == P_TPB - 1) {
        float b0 = softplusf(rb0);
        float b1 = softplusf(rb1);
        float C0 = sqrtf(1.f + b0 * b0);
        float C1 = sqrtf(1.f + b1 * b1);
        if (tid == 0) {
            z0 = C0 * z0 - b0 * exch[2];
            z1 = C1 * z1 - b1 * exch[3];
        } else {
            z0 = C0 * z0 - b0 * exch[0];
            z1 = C1 * z1 - b1 * exch[1];
        }
    }

    // givens_reflection with rot_left
    float f0, f1;
    {
        float n  = fmaxf(sqrtf(l0 * l0 + l1 * l1), 1e-15f);
        float cl = l0 / n, sl = l1 / n;
        f0 = cl * z0 + sl * z1;
        f1 = sl * z0 - cl * z1;
    }
    g_head[b * DIMC + 2 * tid]     = f0;
    g_head[b * DIMC + 2 * tid + 1] = f1;

    if (tid == 0) {
        float nh = sqrtf(f0 * f0 + f1 * f1);
        g_meta[b] = make_float4(f0, f1, nh, bias_head[u]);
    }
}

// ================= kernel 2: TMA-gather tail kernel =================
#define NWARP  4
#define TPB    128
#define YSPLIT 2
#define KBLK   (KC / YSPLIT)              // 64 tails per CTA
#define TAILS_PER_WARP (KBLK / NWARP)     // 16
#define DEPTH  4
#define ROWB   (DIMC * 4)                 // 2048 bytes per row

__global__ __launch_bounds__(TPB)
void tail_kernel(const float* __restrict__ emb,
                 const float* __restrict__ bias_tail,
                 const int*   __restrict__ v_idx,
                 float*       __restrict__ out)
{
    __shared__ __align__(16) float tbuf[NWARP][DEPTH][DIMC];           // 32 KB
    __shared__ __align__(8)  unsigned long long mbar_s[NWARP][DEPTH];  // 128 B
    __shared__ float s_sq[KBLK];
    __shared__ float s_dt[KBLK];
    __shared__ float s_t1[KBLK];

    const int b    = blockIdx.x;
    const int yblk = blockIdx.y;
    const int tid  = threadIdx.x;
    const int lane = tid & 31;
    const int warp = tid >> 5;

    const int kglob0 = yblk * KBLK;
    const int kbase  = warp * TAILS_PER_WARP;

    // init all mbarriers (count=1: the expect_tx arrive), then block-sync
    if (tid < NWARP * DEPTH)
        mbar_init(smem_u32(&mbar_s[tid >> 2][tid & 3]), 1);
    __syncthreads();

    uint32_t bufs[DEPTH], mbars[DEPTH];
    #pragma unroll
    for (int d = 0; d < DEPTH; ++d) {
        bufs[d]  = smem_u32(&tbuf[warp][d][0]);
        mbars[d] = smem_u32(&mbar_s[warp][d]);
    }

    // ---- prime the pipeline: lane 0 issues first DEPTH TMA bulk gathers ----
    if (lane == 0) {
        #pragma unroll
        for (int d = 0; d < DEPTH; ++d) {
            int v0 = v_idx[b * KC + kglob0 + kbase + d];
            mbar_expect_tx(mbars[d], ROWB);
            tma_bulk_g2s(bufs[d], emb + (size_t)v0 * DIMC, ROWB, mbars[d]);
        }
    }

    // ---- head tile from scratch: warp-local, no barrier ----
    const float4* hp = (const float4*)(g_head + (size_t)b * DIMC);
    float4 H0 = hp[0 * 32 + lane];
    float4 H1 = hp[1 * 32 + lane];
    float4 H2 = hp[2 * 32 + lane];
    float4 H3 = hp[3 * 32 + lane];

    // ------- tail loop: 16 tails/warp, TMA ring of DEPTH buffers -------
    #pragma unroll 2
    for (int t = 0; t < TAILS_PER_WARP; ++t) {
        const int slot = t & (DEPTH - 1);
        const uint32_t parity = (t / DEPTH) & 1;
        mbar_wait(mbars[slot], parity);

        const float4* sp = (const float4*)&tbuf[warp][slot][0];
        float4 T0 = sp[0 * 32 + lane];
        float4 T1 = sp[1 * 32 + lane];
        float4 T2 = sp[2 * 32 + lane];
        float4 T3 = sp[3 * 32 + lane];

        // refill this slot with tail t+DEPTH (LDS above already consumed it)
        if (t + DEPTH < TAILS_PER_WARP && lane == 0) {
            int vin = v_idx[b * KC + kglob0 + kbase + t + DEPTH];
            mbar_expect_tx(mbars[slot], ROWB);
            tma_bulk_g2s(bufs[slot], emb + (size_t)vin * DIMC, ROWB, mbars[slot]);
        }

        float sq = T0.x*T0.x + T0.y*T0.y + T0.z*T0.z + T0.w*T0.w
                 + T1.x*T1.x + T1.y*T1.y + T1.z*T1.z + T1.w*T1.w
                 + T2.x*T2.x + T2.y*T2.y + T2.z*T2.z + T2.w*T2.w
                 + T3.x*T3.x + T3.y*T3.y + T3.z*T3.z + T3.w*T3.w;
        float dt = H0.x*T0.x + H0.y*T0.y + H0.z*T0.z + H0.w*T0.w
                 + H1.x*T1.x + H1.y*T1.y + H1.z*T1.z + H1.w*T1.w
                 + H2.x*T2.x + H2.y*T2.y + H2.z*T2.z + H2.w*T2.w
                 + H3.x*T3.x + H3.y*T3.y + H3.z*T3.z + H3.w*T3.w;
        float t1raw = T0.y;   // tail element 1, valid on lane 0
        if (lane == 0) {
            // a_tail = -u1^2 + sum_{j>=2} u_j^2 ; dot only over spatial dims
            sq -= T0.x * T0.x + 2.f * T0.y * T0.y;
            dt -= H0.x * T0.x + H0.y * T0.y;
        }
        // split-half dual reduction: lanes 0-15 reduce sq, lanes 16-31 reduce dt
        {
            float ax = __shfl_xor_sync(0xffffffffu, sq, 16);
            float bx = __shfl_xor_sync(0xffffffffu, dt, 16);
            float v  = (lane < 16) ? (sq + ax) : (dt + bx);
            #pragma unroll
            for (int o = 8; o; o >>= 1) v += __shfl_xor_sync(0xffffffffu, v, o);
            if (lane == 0) {
                s_sq[kbase + t] = v;
                s_t1[kbase + t] = t1raw;
            }
            if (lane == 16) {
                s_dt[kbase + t] = v;
            }
        }
    }
    __syncthreads();

    // ------------- parallel epilogue: threads 0..63 each handle one tail -------------
    if (tid < KBLK) {
        float4 meta = g_meta[b];
        const float h0 = meta.x;
        const float h1 = meta.y;
        const float nh = meta.z;
        const float hb = meta.w;

        float sq    = s_sq[tid];
        float dtv   = s_dt[tid];
        float t1raw = s_t1[tid];

        float ct, stf;
        if (sq > 0.f) {
            float sp = sqrtf(fmaxf(sq, EPSF));
            ct = coshf(sp);  stf = sinhf(sp) / sp;
        } else {
            float st = sqrtf(fmaxf(-sq, EPSF));
            ct = cosf(st);   stf = sinf(st) / st;
        }
        float ty0 = ct;
        float ty1 = stf * t1raw;
        float nt  = sqrtf(ty0 * ty0 + ty1 * ty1);
        float dxy = stf * dtv;

        float cosang = (h0 * ty0 + h1 * ty1) / (nh * nt);
        cosang = fminf(fmaxf(cosang, -1.f + EPSF), 1.f - EPSF);
        float theta = acosf(cosang);

        float inner = nh * nt - dxy;
        float dh = acoshf(fmaxf(inner, 1.f + EPSF));

        float d1 = nh * theta + dh;
        float d2 = nt * theta + dh;
        float dist = fminf(d1 * d1, d2 * d2);

        const int kg = kglob0 + tid;
        int vtail = v_idx[b * KC + kg];
        out[b * KC + kg] = MARGINF - dist + hb + bias_tail[vtail];
    }
}

extern "C" void kernel_launch(void* const* d_in, const int* in_sizes, int n_in,
                              void* d_out, int out_size)
{
    const float* emb       = (const float*)d_in[0];
    const float* rel_boost = (const float*)d_in[1];
    const float* rot_left  = (const float*)d_in[2];
    const float* rot_right = (const float*)d_in[3];
    const float* bias_head = (const float*)d_in[4];
    const float* bias_tail = (const float*)d_in[5];
    const int*   u_idx     = (const int*)d_in[6];
    const int*   r_idx     = (const int*)d_in[7];
    const int*   v_idx     = (const int*)d_in[8];

    head_prep_kernel<<<BC, P_TPB>>>(emb, rel_boost, rot_left, rot_right,
                                    bias_head, u_idx, r_idx);
    dim3 grid(BC, YSPLIT);
    tail_kernel<<<grid, TPB>>>(emb, bias_tail, v_idx, (float*)d_out);
}

// round 14
// speedup vs baseline: 1.5008x; 1.5008x over previous
#include <cuda_runtime.h>
#include <cstdint>

#define DIMC   512
#define BC     512
#define KC     128
#define EPSF   1e-6f
#define MARGINF 2.0f

// ---------------- scratch (static device globals: allocation-free) ----------------
__device__ __align__(16) float  g_head[BC * DIMC];   // transformed head vectors
__device__ __align__(16) float4 g_meta[BC];          // (h0, h1, nh, bias_head[u])

__device__ __forceinline__ float softplusf(float x) {
    return (x > 20.f) ? x : log1pf(expf(x));
}

__device__ __forceinline__ uint64_t mk_evict_last_policy() {
    uint64_t p;
    asm("createpolicy.fractional.L2::evict_last.b64 %0, 1.0;" : "=l"(p));
    return p;
}
__device__ __forceinline__ void cp16_el(uint32_t dst, const void* src, uint64_t pol) {
    asm volatile("cp.async.cg.shared.global.L2::cache_hint [%0], [%1], 16, %2;"
                 :: "r"(dst), "l"(src), "l"(pol));
}
__device__ __forceinline__ void cp_commit() {
    asm volatile("cp.async.commit_group;");
}
template<int N>
__device__ __forceinline__ void cp_wait() {
    asm volatile("cp.async.wait_group %0;" :: "n"(N));
}

// ================= kernel 1: head preprocessing (one block per b) =================
#define P_TPB 256
__global__ __launch_bounds__(P_TPB)
void head_prep_kernel(const float* __restrict__ emb,
                      const float* __restrict__ rel_boost,
                      const float* __restrict__ rot_left,
                      const float* __restrict__ rot_right,
                      const float* __restrict__ bias_head,
                      const int*   __restrict__ u_idx,
                      const int*   __restrict__ r_idx)
{
    __shared__ float red[8];
    __shared__ float exch[4];

    const int b    = blockIdx.x;
    const int tid  = threadIdx.x;
    const int lane = tid & 31;
    const int warp = tid >> 5;
    const int u    = u_idx[b];
    const int r    = r_idx[b];

    const float* hrow = emb + (size_t)u * DIMC;
    float x0 = hrow[2 * tid];
    float x1 = hrow[2 * tid + 1];
    float g0 = rot_right[(size_t)r * DIMC + 2 * tid];
    float g1 = rot_right[(size_t)r * DIMC + 2 * tid + 1];
    float l0 = rot_left[(size_t)r * DIMC + 2 * tid];
    float l1 = rot_left[(size_t)r * DIMC + 2 * tid + 1];
    float rb0 = 0.f, rb1 = 0.f;
    if (tid == 0 || tid == P_TPB - 1) {
        rb0 = rel_boost[2 * r];
        rb1 = rel_boost[2 * r + 1];
    }

    if (tid == 0) x0 = 0.f;                               // proj_tan0
    float acc = (tid == 0) ? (-x1 * x1) : (x0 * x0 + x1 * x1);
    #pragma unroll
    for (int o = 16; o; o >>= 1) acc += __shfl_xor_sync(0xffffffffu, acc, o);
    if (lane == 0) red[warp] = acc;
    __syncthreads();
    float a = 0.f;
    #pragma unroll
    for (int w = 0; w < 8; ++w) a += red[w];

    float c, s;
    if (a > 0.f) {
        float sp = sqrtf(fmaxf(a, EPSF));
        c = coshf(sp);  s = sinhf(sp) / sp;
    } else {
        float st = sqrtf(fmaxf(-a, EPSF));
        c = cosf(st);   s = sinf(st) / st;
    }
    float y0 = (tid == 0) ? c : s * x0;
    float y1 = s * x1;

    // givens_rotations with rot_right
    float z0, z1;
    {
        float n  = fmaxf(sqrtf(g0 * g0 + g1 * g1), 1e-15f);
        float cr = g0 / n, sr = g1 / n;
        z0 = cr * y0 - sr * y1;
        z1 = cr * y1 + sr * y0;
    }

    // Lorentz boost: mixes dims {0,1} (thread 0) with {510,511} (thread 255)
    if (tid == 0)          { exch[0] = z0; exch[1] = z1; }
    if (tid == P_TPB - 1)  { exch[2] = z0; exch[3] = z1; }
    __syncthreads();
    if (tid == 0 || tid == P_TPB - 1) {
        float b0 = softplusf(rb0);
        float b1 = softplusf(rb1);
        float C0 = sqrtf(1.f + b0 * b0);
        float C1 = sqrtf(1.f + b1 * b1);
        if (tid == 0) {
            z0 = C0 * z0 - b0 * exch[2];
            z1 = C1 * z1 - b1 * exch[3];
        } else {
            z0 = C0 * z0 - b0 * exch[0];
            z1 = C1 * z1 - b1 * exch[1];
        }
    }

    // givens_reflection with rot_left
    float f0, f1;
    {
        float n  = fmaxf(sqrtf(l0 * l0 + l1 * l1), 1e-15f);
        float cl = l0 / n, sl = l1 / n;
        f0 = cl * z0 + sl * z1;
        f1 = sl * z0 - cl * z1;
    }
    g_head[b * DIMC + 2 * tid]     = f0;
    g_head[b * DIMC + 2 * tid + 1] = f1;

    if (tid == 0) {
        float nh = sqrtf(f0 * f0 + f1 * f1);
        g_meta[b] = make_float4(f0, f1, nh, bias_head[u]);
    }
}

// ================= kernel 2: balanced tail gather (cp.async + evict_last) =================
#define NWARP  4
#define TPB    128
#define YSPLIT 2
#define KBLK   (KC / YSPLIT)              // 64 tails per CTA
#define TAILS_PER_WARP (KBLK / NWARP)     // 16
#define DEPTH  3

__global__ __launch_bounds__(TPB)
void tail_kernel(const float* __restrict__ emb,
                 const float* __restrict__ bias_tail,
                 const int*   __restrict__ v_idx,
                 float*       __restrict__ out)
{
    __shared__ __align__(16) float tbuf[NWARP][DEPTH][DIMC];   // 24 KB
    __shared__ float s_sq[KBLK];
    __shared__ float s_dt[KBLK];
    __shared__ float s_t1[KBLK];

    const int b    = blockIdx.x;
    const int yblk = blockIdx.y;
    const int tid  = threadIdx.x;
    const int lane = tid & 31;
    const int warp = tid >> 5;

    const int kglob0 = yblk * KBLK;
    const int kbase  = warp * TAILS_PER_WARP;

    const uint64_t pol = mk_evict_last_policy();

    uint32_t bufs[DEPTH];
    #pragma unroll
    for (int d = 0; d < DEPTH; ++d)
        bufs[d] = (uint32_t)__cvta_generic_to_shared(&tbuf[warp][d][0]);

    // ---- prime the gather pipeline ----
    #pragma unroll
    for (int d = 0; d < DEPTH; ++d) {
        int v0 = v_idx[b * KC + kglob0 + kbase + d];
        const float* src = emb + (size_t)v0 * DIMC;
        #pragma unroll
        for (int j = 0; j < 4; ++j)
            cp16_el(bufs[d] + (uint32_t)(j * 512 + lane * 16), src + j * 128 + lane * 4, pol);
        cp_commit();
    }

    // ---- head tile from scratch: warp-local, no barrier ----
    const float4* hp = (const float4*)(g_head + (size_t)b * DIMC);
    float4 H0 = hp[0 * 32 + lane];
    float4 H1 = hp[1 * 32 + lane];
    float4 H2 = hp[2 * 32 + lane];
    float4 H3 = hp[3 * 32 + lane];

    // ------- tail loop: 16 tails/warp, cp.async triple-buffered, distance 3 -------
    int slot = 0;
    #pragma unroll 2
    for (int t = 0; t < TAILS_PER_WARP; ++t) {
        cp_wait<DEPTH - 1>();

        const float4* sp = (const float4*)&tbuf[warp][slot][0];
        float4 T0 = sp[0 * 32 + lane];
        float4 T1 = sp[1 * 32 + lane];
        float4 T2 = sp[2 * 32 + lane];
        float4 T3 = sp[3 * 32 + lane];

        if (t + DEPTH < TAILS_PER_WARP) {
            int vin = v_idx[b * KC + kglob0 + kbase + t + DEPTH];
            const float* src = emb + (size_t)vin * DIMC;
            uint32_t dst = bufs[slot];
            #pragma unroll
            for (int j = 0; j < 4; ++j)
                cp16_el(dst + (uint32_t)(j * 512 + lane * 16), src + j * 128 + lane * 4, pol);
        }
        cp_commit();

        slot = (slot + 1 == DEPTH) ? 0 : slot + 1;

        float sq = T0.x*T0.x + T0.y*T0.y + T0.z*T0.z + T0.w*T0.w
                 + T1.x*T1.x + T1.y*T1.y + T1.z*T1.z + T1.w*T1.w
                 + T2.x*T2.x + T2.y*T2.y + T2.z*T2.z + T2.w*T2.w
                 + T3.x*T3.x + T3.y*T3.y + T3.z*T3.z + T3.w*T3.w;
        float dt = H0.x*T0.x + H0.y*T0.y + H0.z*T0.z + H0.w*T0.w
                 + H1.x*T1.x + H1.y*T1.y + H1.z*T1.z + H1.w*T1.w
                 + H2.x*T2.x + H2.y*T2.y + H2.z*T2.z + H2.w*T2.w
                 + H3.x*T3.x + H3.y*T3.y + H3.z*T3.z + H3.w*T3.w;
        float t1raw = T0.y;   // tail element 1, valid on lane 0
        if (lane == 0) {
            // a_tail = -u1^2 + sum_{j>=2} u_j^2 ; dot only over spatial dims
            sq -= T0.x * T0.x + 2.f * T0.y * T0.y;
            dt -= H0.x * T0.x + H0.y * T0.y;
        }
        // split-half dual reduction: lanes 0-15 reduce sq, lanes 16-31 reduce dt
        {
            float ax = __shfl_xor_sync(0xffffffffu, sq, 16);
            float bx = __shfl_xor_sync(0xffffffffu, dt, 16);
            float v  = (lane < 16) ? (sq + ax) : (dt + bx);
            #pragma unroll
            for (int o = 8; o; o >>= 1) v += __shfl_xor_sync(0xffffffffu, v, o);
            if (lane == 0) {
                s_sq[kbase + t] = v;
                s_t1[kbase + t] = t1raw;
            }
            if (lane == 16) {
                s_dt[kbase + t] = v;
            }
        }
    }
    __syncthreads();

    // ------------- parallel epilogue: threads 0..63 each handle one tail -------------
    if (tid < KBLK) {
        float4 meta = g_meta[b];
        const float h0 = meta.x;
        const float h1 = meta.y;
        const float nh = meta.z;
        const float hb = meta.w;

        float sq    = s_sq[tid];
        float dtv   = s_dt[tid];
        float t1raw = s_t1[tid];

        float ct, stf;
        if (sq > 0.f) {
            float sp = sqrtf(fmaxf(sq, EPSF));
            ct = coshf(sp);  stf = sinhf(sp) / sp;
        } else {
            float st = sqrtf(fmaxf(-sq, EPSF));
            ct = cosf(st);   stf = sinf(st) / st;
        }
        float ty0 = ct;
        float ty1 = stf * t1raw;
        float nt  = sqrtf(ty0 * ty0 + ty1 * ty1);
        float dxy = stf * dtv;

        float cosang = (h0 * ty0 + h1 * ty1) / (nh * nt);
        cosang = fminf(fmaxf(cosang, -1.f + EPSF), 1.f - EPSF);
        float theta = acosf(cosang);

        float inner = nh * nt - dxy;
        float dh = acoshf(fmaxf(inner, 1.f + EPSF));

        float d1 = nh * theta + dh;
        float d2 = nt * theta + dh;
        float dist = fminf(d1 * d1, d2 * d2);

        const int kg = kglob0 + tid;
        int vtail = v_idx[b * KC + kg];
        out[b * KC + kg] = MARGINF - dist + hb + bias_tail[vtail];
    }
}

extern "C" void kernel_launch(void* const* d_in, const int* in_sizes, int n_in,
                              void* d_out, int out_size)
{
    const float* emb       = (const float*)d_in[0];
    const float* rel_boost = (const float*)d_in[1];
    const float* rot_left  = (const float*)d_in[2];
    const float* rot_right = (const float*)d_in[3];
    const float* bias_head = (const float*)d_in[4];
    const float* bias_tail = (const float*)d_in[5];
    const int*   u_idx     = (const int*)d_in[6];
    const int*   r_idx     = (const int*)d_in[7];
    const int*   v_idx     = (const int*)d_in[8];

    head_prep_kernel<<<BC, P_TPB>>>(emb, rel_boost, rot_left, rot_right,
                                    bias_head, u_idx, r_idx);
    dim3 grid(BC, YSPLIT);
    tail_kernel<<<grid, TPB>>>(emb, bias_tail, v_idx, (float*)d_out);
}